// round 11
// baseline (speedup 1.0000x reference)
#include <cuda_runtime.h>
#include <cuda_fp16.h>
#include <cstdint>

#define HID 128
#define MAXN 50176
#define MAXE 1605632
#define SCAN_BLOCKS 64

__device__ __align__(16) __half g_hh [(size_t)MAXN * HID];  // layer-0 features (fp16)
__device__ __align__(16) __half g_hbh[(size_t)MAXN * HID];  // layer-1 features (fp16)
__device__ float g_si [MAXN];   // layer-1 attention scalars
__device__ float g_sj [MAXN];
__device__ float g_si2[MAXN];   // layer-2 attention scalars
__device__ float g_sj2[MAXN];
__device__ int   g_deg[MAXN];   // INVARIANT: all-zero at kernel_launch entry
__device__ int   g_start[MAXN];
__device__ int   g_cursor[MAXN];
__device__ int   g_sorted[MAXE];
__device__ int   g_bsum[SCAN_BLOCKS];

// ---------------------------------------------------------------------------
// Inline edge-dtype detection (per warp): odd int32 words of int64 data
// (values < 50000, little-endian) are all zero.
// ---------------------------------------------------------------------------
__device__ __forceinline__ int detect_is64(const int* __restrict__ p) {
    int lane = threadIdx.x & 31;
    unsigned v = 0;
#pragma unroll
    for (int j = 0; j < 4; j++)
        v |= (unsigned)p[2 * (lane * 4 + j) + 1];
    unsigned any = __ballot_sync(0xFFFFFFFFu, v != 0);
    return any == 0;
}

// ---------------------------------------------------------------------------
// GEMM helpers (fp16 mma, fp32 accum)
// ---------------------------------------------------------------------------
__device__ __forceinline__ void ldsm_x4(unsigned* a, uint32_t addr) {
    asm volatile("ldmatrix.sync.aligned.m8n8.x4.shared.b16 {%0,%1,%2,%3}, [%4];"
                 : "=r"(a[0]), "=r"(a[1]), "=r"(a[2]), "=r"(a[3]) : "r"(addr));
}
__device__ __forceinline__ void ldsm_x2_trans(unsigned* b, uint32_t addr) {
    asm volatile("ldmatrix.sync.aligned.m8n8.x2.trans.shared.b16 {%0,%1}, [%2];"
                 : "=r"(b[0]), "=r"(b[1]) : "r"(addr));
}
__device__ __forceinline__ void mma16816(float* c, const unsigned* a, const unsigned* b) {
    asm volatile("mma.sync.aligned.m16n8k16.row.col.f32.f16.f16.f32 "
                 "{%0,%1,%2,%3}, {%4,%5,%6,%7}, {%8,%9}, {%0,%1,%2,%3};"
                 : "+f"(c[0]), "+f"(c[1]), "+f"(c[2]), "+f"(c[3])
                 : "r"(a[0]), "r"(a[1]), "r"(a[2]), "r"(a[3]),
                   "r"(b[0]), "r"(b[1]));
}

// ---------------------------------------------------------------------------
// Mega-kernel A: blocks [0,Ggemm) = encoder GEMM; the rest = dst histogram.
// ---------------------------------------------------------------------------
__global__ void __launch_bounds__(256) gemm_hist_kernel(
        const float* __restrict__ A, const float* __restrict__ W,
        const float* __restrict__ bias, const int* __restrict__ ei,
        int M, int E, int Ggemm) {
    const int LDA = 40;
    const int LDB = 136;
    __shared__ __half As[128 * LDA];
    __shared__ __half Bs[32 * LDB];

    if (blockIdx.x >= Ggemm) {
        int is64 = detect_is64(ei);
        int base = (blockIdx.x - Ggemm) * 2048 + threadIdx.x;
#pragma unroll
        for (int i = 0; i < 8; i++) {
            int e = base + i * 256;
            if (e < E) {
                int d = is64 ? ei[2 * (E + e)] : ei[E + e];
                atomicAdd(&g_deg[d], 1);
            }
        }
        return;
    }

    int tid = threadIdx.x;
    int warp = tid >> 5;
    int lane = tid & 31;
    int warp_m = warp >> 2;
    int warp_n = warp & 3;
    int bm = blockIdx.x * 128;

    uint32_t sA = (uint32_t)__cvta_generic_to_shared(As);
    uint32_t sB = (uint32_t)__cvta_generic_to_shared(Bs);

    float c[4][4][4];
#pragma unroll
    for (int mt = 0; mt < 4; mt++)
#pragma unroll
        for (int nt = 0; nt < 4; nt++)
#pragma unroll
            for (int r = 0; r < 4; r++) c[mt][nt][r] = 0.f;

    for (int k0 = 0; k0 < 256; k0 += 32) {
#pragma unroll
        for (int i = 0; i < 4; i++) {
            int t = tid + i * 256;
            int r = t >> 3;
            int c4 = t & 7;
            int row = bm + r;
            float4 v = make_float4(0.f, 0.f, 0.f, 0.f);
            if (row < M)
                v = *(const float4*)(A + (size_t)row * 256 + k0 + c4 * 4);
            __half2 h01 = __floats2half2_rn(v.x, v.y);
            __half2 h23 = __floats2half2_rn(v.z, v.w);
            uint2 u = make_uint2(*(unsigned*)&h01, *(unsigned*)&h23);
            *(uint2*)(As + r * LDA + c4 * 4) = u;
        }
#pragma unroll
        for (int i = 0; i < 4; i++) {
            int t = tid + i * 256;
            int r = t >> 5;
            int c4 = t & 31;
            float4 v = *(const float4*)(W + (size_t)(k0 + r) * 128 + c4 * 4);
            __half2 h01 = __floats2half2_rn(v.x, v.y);
            __half2 h23 = __floats2half2_rn(v.z, v.w);
            uint2 u = make_uint2(*(unsigned*)&h01, *(unsigned*)&h23);
            *(uint2*)(Bs + r * LDB + c4 * 4) = u;
        }
        __syncthreads();
#pragma unroll
        for (int ks = 0; ks < 2; ks++) {
            int ko = ks * 16;
            unsigned a[4][4], b[4][2];
#pragma unroll
            for (int mt = 0; mt < 4; mt++) {
                uint32_t addr = sA + 2u * (uint32_t)((warp_m * 64 + mt * 16 + (lane & 15)) * LDA
                                           + ko + (lane >> 4) * 8);
                ldsm_x4(a[mt], addr);
            }
#pragma unroll
            for (int nt = 0; nt < 4; nt++) {
                uint32_t addr = sB + 2u * (uint32_t)((ko + (lane & 15)) * LDB
                                           + warp_n * 32 + nt * 8);
                ldsm_x2_trans(b[nt], addr);
            }
#pragma unroll
            for (int mt = 0; mt < 4; mt++)
#pragma unroll
                for (int nt = 0; nt < 4; nt++)
                    mma16816(c[mt][nt], a[mt], b[nt]);
        }
        __syncthreads();
    }

#pragma unroll
    for (int nt = 0; nt < 4; nt++) {
        int col = warp_n * 32 + nt * 8 + (lane & 3) * 2;
        float b0 = __ldg(bias + col);
        float b1 = __ldg(bias + col + 1);
#pragma unroll
        for (int mt = 0; mt < 4; mt++) {
            int row = bm + warp_m * 64 + mt * 16 + (lane >> 2);
            if (row < M) {
                float v0 = c[mt][nt][0] + b0;
                float v1 = c[mt][nt][1] + b1;
                __half2 h = __floats2half2_rn(v0 > 0.f ? v0 : 0.f,
                                              v1 > 0.f ? v1 : 0.f);
                *(__half2*)(g_hh + (size_t)row * HID + col) = h;
            }
            if (row + 8 < M) {
                float v0 = c[mt][nt][2] + b0;
                float v1 = c[mt][nt][3] + b1;
                __half2 h = __floats2half2_rn(v0 > 0.f ? v0 : 0.f,
                                              v1 > 0.f ? v1 : 0.f);
                *(__half2*)(g_hh + (size_t)(row + 8) * HID + col) = h;
            }
        }
    }
}

// ---------------------------------------------------------------------------
// CSR scan stages
// ---------------------------------------------------------------------------
__global__ void scan_block_kernel(int n) {
    __shared__ int warp_tot[32];
    int tid = threadIdx.x;
    int lane = tid & 31;
    int wid = tid >> 5;
    int i = blockIdx.x * 1024 + tid;
    int v = (i < n) ? g_deg[i] : 0;
    int x = v;
#pragma unroll
    for (int o = 1; o < 32; o <<= 1) {
        int y = __shfl_up_sync(0xFFFFFFFFu, x, o);
        if (lane >= o) x += y;
    }
    if (lane == 31) warp_tot[wid] = x;
    __syncthreads();
    if (wid == 0) {
        int t = warp_tot[lane];
#pragma unroll
        for (int o = 1; o < 32; o <<= 1) {
            int y = __shfl_up_sync(0xFFFFFFFFu, t, o);
            if (lane >= o) t += y;
        }
        warp_tot[lane] = t;
    }
    __syncthreads();
    int off = wid ? warp_tot[wid - 1] : 0;
    int incl = x + off;
    if (i < n) g_start[i] = incl - v;
    if (tid == 1023) g_bsum[blockIdx.x] = incl;
}

__global__ void add_off_kernel(int n, int nb) {
    __shared__ int boff_s;
    int tid = threadIdx.x;
    int b = blockIdx.x;
    if (tid < 32) {
        int acc = 0;
#pragma unroll
        for (int j = 0; j < 2; j++) {
            int idx = tid + j * 32;
            if (idx < b && idx < nb) acc += g_bsum[idx];
        }
#pragma unroll
        for (int o = 16; o; o >>= 1)
            acc += __shfl_xor_sync(0xFFFFFFFFu, acc, o);
        if (tid == 0) boff_s = acc;
    }
    __syncthreads();
    int i = b * 1024 + tid;
    if (i < n) {
        int s = g_start[i] + boff_s;
        g_start[i] = s;
        g_cursor[i] = s;
    }
}

// ---------------------------------------------------------------------------
// Mega-kernel B: blocks [0,Gs) = CSR scatter; rest = layer-1 dots.
// ---------------------------------------------------------------------------
__global__ void __launch_bounds__(256) scatter_dots_kernel(
        const int* __restrict__ ei, const float* __restrict__ w,
        int E, int n, int Gs) {
    if (blockIdx.x < Gs) {
        int is64 = detect_is64(ei);
        int base = blockIdx.x * 2048 + threadIdx.x;
#pragma unroll
        for (int i = 0; i < 8; i++) {
            int e = base + i * 256;
            if (e < E) {
                int s, d;
                if (is64) { s = ei[2 * e]; d = ei[2 * (E + e)]; }
                else      { s = ei[e];     d = ei[E + e]; }
                int pos = atomicAdd(&g_cursor[d], 1);
                g_sorted[pos] = s;
            }
        }
        return;
    }
    int node = (blockIdx.x - Gs) * 8 + (threadIdx.x >> 5);
    int lane = threadIdx.x & 31;
    if (node >= n) return;
    uint2 raw = *((const uint2*)(g_hh + (size_t)node * HID) + lane);
    float2 f01 = __half22float2(*(__half2*)&raw.x);
    float2 f23 = __half22float2(*(__half2*)&raw.y);
    float4 wi = ((const float4*)w)[lane];
    float4 wj = ((const float4*)w)[32 + lane];
    float si = f01.x * wi.x + f01.y * wi.y + f23.x * wi.z + f23.y * wi.w;
    float sj = f01.x * wj.x + f01.y * wj.y + f23.x * wj.z + f23.y * wj.w;
#pragma unroll
    for (int o = 16; o; o >>= 1) {
        si += __shfl_xor_sync(0xFFFFFFFFu, si, o);
        sj += __shfl_xor_sync(0xFFFFFFFFu, sj, o);
    }
    if (lane == 0) { g_si[node] = si; g_sj[node] = sj; }
}

// ---------------------------------------------------------------------------
// Gather-accumulate (R7 layout: 2 edges/warp, 16 lanes/edge, one uint4/lane)
// with cooperative index staging: all 32 lanes load g_sorted[kb+lane] once
// per 32-edge chunk; per-trip src ids come from __shfl (register-resident),
// removing the per-trip pointer chase so feature/sj loads batch freely.
// After xor(16) ALL lanes hold full sums for features [sub*8, sub*8+8).
// ---------------------------------------------------------------------------
__device__ __forceinline__ void agg_accum(const __half* __restrict__ feat,
                                          const float* __restrict__ sj_tab,
                                          int k0, int deg, float sib,
                                          int lane, float* acc) {
    int half = lane >> 4;
#pragma unroll
    for (int r = 0; r < 8; r++) acc[r] = 0.f;
    int sub = lane & 15;
    int kend = k0 + deg;
    for (int kb = k0; kb < kend; kb += 32) {
        int idx = kb + lane;
        int sload = (idx < kend) ? g_sorted[idx] : 0;
        int trips = kend - kb;
        if (trips > 32) trips = 32;
        int nt = (trips + 1) >> 1;   // pair count; groups may pad last pair
#pragma unroll 16
        for (int t2 = 0; t2 < nt; t2++) {
            int t = 2 * t2 + half;
            int s = __shfl_sync(0xFFFFFFFFu, sload, t);
            if (t < trips) {
                float z = sib + __ldg(sj_tab + s);
                float alpha = 1.0f / (1.0f + __expf(-z));
                uint4 raw = *((const uint4*)(feat + (size_t)s * HID) + sub);
                float2 f;
                f = __half22float2(*(__half2*)&raw.x);
                acc[0] += alpha * f.x; acc[1] += alpha * f.y;
                f = __half22float2(*(__half2*)&raw.y);
                acc[2] += alpha * f.x; acc[3] += alpha * f.y;
                f = __half22float2(*(__half2*)&raw.z);
                acc[4] += alpha * f.x; acc[5] += alpha * f.y;
                f = __half22float2(*(__half2*)&raw.w);
                acc[6] += alpha * f.x; acc[7] += alpha * f.y;
            }
        }
    }
#pragma unroll
    for (int r = 0; r < 8; r++)
        acc[r] += __shfl_xor_sync(0xFFFFFFFFu, acc[r], 16);
}

// ---------------------------------------------------------------------------
// Layer 1 + fused layer-2 dots:
// g_hbh[d] = fp16(relu(acc/max(deg,1))); g_si2/g_sj2[d] from the rounded hb.
// ---------------------------------------------------------------------------
__global__ void agg1_kernel(const float* __restrict__ bptr,
                            const float* __restrict__ att2w, int n) {
    int d = (blockIdx.x * blockDim.x + threadIdx.x) >> 5;
    int lane = threadIdx.x & 31;
    if (d >= n) return;
    int half = lane >> 4, sub = lane & 15;
    float acc[8];
    float sib = g_si[d] + bptr[0];
    int deg = g_deg[d];
    agg_accum(g_hh, g_sj, g_start[d], deg, sib, lane, acc);
    float inv = 1.0f / (float)(deg < 1 ? 1 : deg);
    __half2 h01 = __floats2half2_rn(fmaxf(acc[0] * inv, 0.f), fmaxf(acc[1] * inv, 0.f));
    __half2 h23 = __floats2half2_rn(fmaxf(acc[2] * inv, 0.f), fmaxf(acc[3] * inv, 0.f));
    __half2 h45 = __floats2half2_rn(fmaxf(acc[4] * inv, 0.f), fmaxf(acc[5] * inv, 0.f));
    __half2 h67 = __floats2half2_rn(fmaxf(acc[6] * inv, 0.f), fmaxf(acc[7] * inv, 0.f));
    if (half == 0) {
        uint4 u;
        u.x = *(unsigned*)&h01; u.y = *(unsigned*)&h23;
        u.z = *(unsigned*)&h45; u.w = *(unsigned*)&h67;
        *((uint4*)(g_hbh + (size_t)d * HID) + sub) = u;
    }
    // fused layer-2 dots from the fp16-rounded values
    float f[8];
    float2 t;
    t = __half22float2(h01); f[0] = t.x; f[1] = t.y;
    t = __half22float2(h23); f[2] = t.x; f[3] = t.y;
    t = __half22float2(h45); f[4] = t.x; f[5] = t.y;
    t = __half22float2(h67); f[6] = t.x; f[7] = t.y;
    int j = sub * 8;
    float4 wi0 = *(const float4*)(att2w + j);
    float4 wi1 = *(const float4*)(att2w + j + 4);
    float4 wj0 = *(const float4*)(att2w + 128 + j);
    float4 wj1 = *(const float4*)(att2w + 128 + j + 4);
    float si = f[0]*wi0.x + f[1]*wi0.y + f[2]*wi0.z + f[3]*wi0.w
             + f[4]*wi1.x + f[5]*wi1.y + f[6]*wi1.z + f[7]*wi1.w;
    float sj = f[0]*wj0.x + f[1]*wj0.y + f[2]*wj0.z + f[3]*wj0.w
             + f[4]*wj1.x + f[5]*wj1.y + f[6]*wj1.z + f[7]*wj1.w;
    if (half) { si = 0.f; sj = 0.f; }
#pragma unroll
    for (int o = 16; o; o >>= 1) {
        si += __shfl_xor_sync(0xFFFFFFFFu, si, o);
        sj += __shfl_xor_sync(0xFFFFFFFFu, sj, o);
    }
    if (lane == 0) { g_si2[d] = si; g_sj2[d] = sj; }
}

// ---------------------------------------------------------------------------
// Layer 2 + classifier; restores the g_deg==0 invariant for graph replay.
// ---------------------------------------------------------------------------
__global__ void agg2_cls_kernel(const float* __restrict__ bptr,
                                const float* __restrict__ clsw,
                                const float* __restrict__ clsb,
                                float* __restrict__ out, int n) {
    int d = (blockIdx.x * blockDim.x + threadIdx.x) >> 5;
    int lane = threadIdx.x & 31;
    if (d >= n) return;
    int sub = lane & 15;
    float acc[8];
    float sib = g_si2[d] + bptr[0];
    int deg = g_deg[d];
    if (lane == 0) g_deg[d] = 0;   // restore invariant for next replay
    agg_accum(g_hbh, g_sj2, g_start[d], deg, sib, lane, acc);
    float inv = 1.0f / (float)(deg < 1 ? 1 : deg);
    float o0 = 0.f, o1 = 0.f;
#pragma unroll
    for (int r = 0; r < 8; r++) {
        float v = acc[r] * inv;
        int j = sub * 8 + r;
        o0 += v * clsw[j * 2];
        o1 += v * clsw[j * 2 + 1];
    }
#pragma unroll
    for (int o = 8; o; o >>= 1) {
        o0 += __shfl_xor_sync(0xFFFFFFFFu, o0, o);
        o1 += __shfl_xor_sync(0xFFFFFFFFu, o1, o);
    }
    if (lane == 0) {
        out[(size_t)d * 2 + 0] = o0 + clsb[0];
        out[(size_t)d * 2 + 1] = o1 + clsb[1];
    }
}

// ---------------------------------------------------------------------------
extern "C" void kernel_launch(void* const* d_in, const int* in_sizes, int n_in,
                              void* d_out, int out_size) {
    const float* x      = (const float*)d_in[0];
    const int*   ei     = (const int*)  d_in[1];
    const float* enc_w  = (const float*)d_in[2];
    const float* enc_b  = (const float*)d_in[3];
    const float* att1_w = (const float*)d_in[4];
    const float* att1_b = (const float*)d_in[5];
    const float* att2_w = (const float*)d_in[6];
    const float* att2_b = (const float*)d_in[7];
    const float* cls_w  = (const float*)d_in[8];
    const float* cls_b  = (const float*)d_in[9];
    float* out = (float*)d_out;

    int N = in_sizes[0] / 256;
    int E = in_sizes[1] / 2;
    int nb = (N + 1023) / 1024;
    int Ggemm = (N + 127) / 128;
    int Gh = (E + 2047) / 2048;
    int Gd = (N + 7) / 8;

    // A: encoder GEMM (tensor cores) overlapped with dst histogram
    gemm_hist_kernel<<<Ggemm + Gh, 256>>>(x, enc_w, enc_b, ei, N, E, Ggemm);
    // CSR offsets
    scan_block_kernel<<<nb, 1024>>>(N);
    add_off_kernel<<<nb, 1024>>>(N, nb);
    // B: CSR scatter overlapped with layer-1 attention dots
    scatter_dots_kernel<<<Gh + Gd, 256>>>(ei, att1_w, E, N, Gh);
    // Layer 1 (+ fused layer-2 dots)
    agg1_kernel<<<Gd, 256>>>(att1_b, att2_w, N);
    // Layer 2 + classifier (+ deg invariant restore)
    agg2_cls_kernel<<<Gd, 256>>>(att2_b, cls_w, cls_b, out, N);
}

// round 12
// speedup vs baseline: 1.1207x; 1.1207x over previous
#include <cuda_runtime.h>
#include <cuda_fp16.h>
#include <cstdint>

#define HID 128
#define MAXN 50176
#define MAXE 1605632
#define SCAN_BLOCKS 64

__device__ __align__(16) __half g_hh [(size_t)MAXN * HID];  // layer-0 features (fp16)
__device__ __align__(16) __half g_hbh[(size_t)MAXN * HID];  // layer-1 features (fp16)
__device__ float g_si [MAXN];   // layer-1 attention scalars
__device__ float g_sj [MAXN];
__device__ float g_si2[MAXN];   // layer-2 attention scalars
__device__ float g_sj2[MAXN];
__device__ int   g_deg[MAXN];   // INVARIANT: all-zero at kernel_launch entry
__device__ int   g_start[MAXN];
__device__ int   g_cursor[MAXN];
__device__ int   g_sorted[MAXE];
__device__ int   g_bsum[SCAN_BLOCKS];

// ---------------------------------------------------------------------------
// Inline edge-dtype detection (per warp): odd int32 words of int64 data
// (values < 50000, little-endian) are all zero.
// ---------------------------------------------------------------------------
__device__ __forceinline__ int detect_is64(const int* __restrict__ p) {
    int lane = threadIdx.x & 31;
    unsigned v = 0;
#pragma unroll
    for (int j = 0; j < 4; j++)
        v |= (unsigned)p[2 * (lane * 4 + j) + 1];
    unsigned any = __ballot_sync(0xFFFFFFFFu, v != 0);
    return any == 0;
}

// ---------------------------------------------------------------------------
// GEMM helpers (fp16 mma, fp32 accum)
// ---------------------------------------------------------------------------
__device__ __forceinline__ void ldsm_x4(unsigned* a, uint32_t addr) {
    asm volatile("ldmatrix.sync.aligned.m8n8.x4.shared.b16 {%0,%1,%2,%3}, [%4];"
                 : "=r"(a[0]), "=r"(a[1]), "=r"(a[2]), "=r"(a[3]) : "r"(addr));
}
__device__ __forceinline__ void ldsm_x2_trans(unsigned* b, uint32_t addr) {
    asm volatile("ldmatrix.sync.aligned.m8n8.x2.trans.shared.b16 {%0,%1}, [%2];"
                 : "=r"(b[0]), "=r"(b[1]) : "r"(addr));
}
__device__ __forceinline__ void mma16816(float* c, const unsigned* a, const unsigned* b) {
    asm volatile("mma.sync.aligned.m16n8k16.row.col.f32.f16.f16.f32 "
                 "{%0,%1,%2,%3}, {%4,%5,%6,%7}, {%8,%9}, {%0,%1,%2,%3};"
                 : "+f"(c[0]), "+f"(c[1]), "+f"(c[2]), "+f"(c[3])
                 : "r"(a[0]), "r"(a[1]), "r"(a[2]), "r"(a[3]),
                   "r"(b[0]), "r"(b[1]));
}

// ---------------------------------------------------------------------------
// Mega-kernel A: blocks [0,Ggemm) = encoder GEMM; the rest = dst histogram.
// ---------------------------------------------------------------------------
__global__ void __launch_bounds__(256) gemm_hist_kernel(
        const float* __restrict__ A, const float* __restrict__ W,
        const float* __restrict__ bias, const int* __restrict__ ei,
        int M, int E, int Ggemm) {
    const int LDA = 40;
    const int LDB = 136;
    __shared__ __half As[128 * LDA];
    __shared__ __half Bs[32 * LDB];

    if (blockIdx.x >= Ggemm) {
        int is64 = detect_is64(ei);
        int base = (blockIdx.x - Ggemm) * 2048 + threadIdx.x;
#pragma unroll
        for (int i = 0; i < 8; i++) {
            int e = base + i * 256;
            if (e < E) {
                int d = is64 ? ei[2 * (E + e)] : ei[E + e];
                atomicAdd(&g_deg[d], 1);
            }
        }
        return;
    }

    int tid = threadIdx.x;
    int warp = tid >> 5;
    int lane = tid & 31;
    int warp_m = warp >> 2;
    int warp_n = warp & 3;
    int bm = blockIdx.x * 128;

    uint32_t sA = (uint32_t)__cvta_generic_to_shared(As);
    uint32_t sB = (uint32_t)__cvta_generic_to_shared(Bs);

    float c[4][4][4];
#pragma unroll
    for (int mt = 0; mt < 4; mt++)
#pragma unroll
        for (int nt = 0; nt < 4; nt++)
#pragma unroll
            for (int r = 0; r < 4; r++) c[mt][nt][r] = 0.f;

    for (int k0 = 0; k0 < 256; k0 += 32) {
#pragma unroll
        for (int i = 0; i < 4; i++) {
            int t = tid + i * 256;
            int r = t >> 3;
            int c4 = t & 7;
            int row = bm + r;
            float4 v = make_float4(0.f, 0.f, 0.f, 0.f);
            if (row < M)
                v = *(const float4*)(A + (size_t)row * 256 + k0 + c4 * 4);
            __half2 h01 = __floats2half2_rn(v.x, v.y);
            __half2 h23 = __floats2half2_rn(v.z, v.w);
            uint2 u = make_uint2(*(unsigned*)&h01, *(unsigned*)&h23);
            *(uint2*)(As + r * LDA + c4 * 4) = u;
        }
#pragma unroll
        for (int i = 0; i < 4; i++) {
            int t = tid + i * 256;
            int r = t >> 5;
            int c4 = t & 31;
            float4 v = *(const float4*)(W + (size_t)(k0 + r) * 128 + c4 * 4);
            __half2 h01 = __floats2half2_rn(v.x, v.y);
            __half2 h23 = __floats2half2_rn(v.z, v.w);
            uint2 u = make_uint2(*(unsigned*)&h01, *(unsigned*)&h23);
            *(uint2*)(Bs + r * LDB + c4 * 4) = u;
        }
        __syncthreads();
#pragma unroll
        for (int ks = 0; ks < 2; ks++) {
            int ko = ks * 16;
            unsigned a[4][4], b[4][2];
#pragma unroll
            for (int mt = 0; mt < 4; mt++) {
                uint32_t addr = sA + 2u * (uint32_t)((warp_m * 64 + mt * 16 + (lane & 15)) * LDA
                                           + ko + (lane >> 4) * 8);
                ldsm_x4(a[mt], addr);
            }
#pragma unroll
            for (int nt = 0; nt < 4; nt++) {
                uint32_t addr = sB + 2u * (uint32_t)((ko + (lane & 15)) * LDB
                                           + warp_n * 32 + nt * 8);
                ldsm_x2_trans(b[nt], addr);
            }
#pragma unroll
            for (int mt = 0; mt < 4; mt++)
#pragma unroll
                for (int nt = 0; nt < 4; nt++)
                    mma16816(c[mt][nt], a[mt], b[nt]);
        }
        __syncthreads();
    }

#pragma unroll
    for (int nt = 0; nt < 4; nt++) {
        int col = warp_n * 32 + nt * 8 + (lane & 3) * 2;
        float b0 = __ldg(bias + col);
        float b1 = __ldg(bias + col + 1);
#pragma unroll
        for (int mt = 0; mt < 4; mt++) {
            int row = bm + warp_m * 64 + mt * 16 + (lane >> 2);
            if (row < M) {
                float v0 = c[mt][nt][0] + b0;
                float v1 = c[mt][nt][1] + b1;
                __half2 h = __floats2half2_rn(v0 > 0.f ? v0 : 0.f,
                                              v1 > 0.f ? v1 : 0.f);
                *(__half2*)(g_hh + (size_t)row * HID + col) = h;
            }
            if (row + 8 < M) {
                float v0 = c[mt][nt][2] + b0;
                float v1 = c[mt][nt][3] + b1;
                __half2 h = __floats2half2_rn(v0 > 0.f ? v0 : 0.f,
                                              v1 > 0.f ? v1 : 0.f);
                *(__half2*)(g_hh + (size_t)(row + 8) * HID + col) = h;
            }
        }
    }
}

// ---------------------------------------------------------------------------
// CSR scan stages
// ---------------------------------------------------------------------------
__global__ void scan_block_kernel(int n) {
    __shared__ int warp_tot[32];
    int tid = threadIdx.x;
    int lane = tid & 31;
    int wid = tid >> 5;
    int i = blockIdx.x * 1024 + tid;
    int v = (i < n) ? g_deg[i] : 0;
    int x = v;
#pragma unroll
    for (int o = 1; o < 32; o <<= 1) {
        int y = __shfl_up_sync(0xFFFFFFFFu, x, o);
        if (lane >= o) x += y;
    }
    if (lane == 31) warp_tot[wid] = x;
    __syncthreads();
    if (wid == 0) {
        int t = warp_tot[lane];
#pragma unroll
        for (int o = 1; o < 32; o <<= 1) {
            int y = __shfl_up_sync(0xFFFFFFFFu, t, o);
            if (lane >= o) t += y;
        }
        warp_tot[lane] = t;
    }
    __syncthreads();
    int off = wid ? warp_tot[wid - 1] : 0;
    int incl = x + off;
    if (i < n) g_start[i] = incl - v;
    if (tid == 1023) g_bsum[blockIdx.x] = incl;
}

__global__ void add_off_kernel(int n, int nb) {
    __shared__ int boff_s;
    int tid = threadIdx.x;
    int b = blockIdx.x;
    if (tid < 32) {
        int acc = 0;
#pragma unroll
        for (int j = 0; j < 2; j++) {
            int idx = tid + j * 32;
            if (idx < b && idx < nb) acc += g_bsum[idx];
        }
#pragma unroll
        for (int o = 16; o; o >>= 1)
            acc += __shfl_xor_sync(0xFFFFFFFFu, acc, o);
        if (tid == 0) boff_s = acc;
    }
    __syncthreads();
    int i = b * 1024 + tid;
    if (i < n) {
        int s = g_start[i] + boff_s;
        g_start[i] = s;
        g_cursor[i] = s;
    }
}

// ---------------------------------------------------------------------------
// Mega-kernel B: blocks [0,Gs) = CSR scatter; rest = layer-1 dots.
// ---------------------------------------------------------------------------
__global__ void __launch_bounds__(256) scatter_dots_kernel(
        const int* __restrict__ ei, const float* __restrict__ w,
        int E, int n, int Gs) {
    if (blockIdx.x < Gs) {
        int is64 = detect_is64(ei);
        int base = blockIdx.x * 2048 + threadIdx.x;
#pragma unroll
        for (int i = 0; i < 8; i++) {
            int e = base + i * 256;
            if (e < E) {
                int s, d;
                if (is64) { s = ei[2 * e]; d = ei[2 * (E + e)]; }
                else      { s = ei[e];     d = ei[E + e]; }
                int pos = atomicAdd(&g_cursor[d], 1);
                g_sorted[pos] = s;
            }
        }
        return;
    }
    int node = (blockIdx.x - Gs) * 8 + (threadIdx.x >> 5);
    int lane = threadIdx.x & 31;
    if (node >= n) return;
    uint2 raw = *((const uint2*)(g_hh + (size_t)node * HID) + lane);
    float2 f01 = __half22float2(*(__half2*)&raw.x);
    float2 f23 = __half22float2(*(__half2*)&raw.y);
    float4 wi = ((const float4*)w)[lane];
    float4 wj = ((const float4*)w)[32 + lane];
    float si = f01.x * wi.x + f01.y * wi.y + f23.x * wi.z + f23.y * wi.w;
    float sj = f01.x * wj.x + f01.y * wj.y + f23.x * wj.z + f23.y * wj.w;
#pragma unroll
    for (int o = 16; o; o >>= 1) {
        si += __shfl_xor_sync(0xFFFFFFFFu, si, o);
        sj += __shfl_xor_sync(0xFFFFFFFFu, sj, o);
    }
    if (lane == 0) { g_si[node] = si; g_sj[node] = sj; }
}

// ---------------------------------------------------------------------------
// Gather-accumulate (R7 layout, sacred): 2 edges per warp step, 16 lanes/edge,
// one uint4 (8-half) load per lane. After xor(16) ALL lanes hold full sums
// for features [sub*8, sub*8+8), sub = lane&15. Only change vs R7: unroll 8.
// ---------------------------------------------------------------------------
__device__ __forceinline__ void agg_accum(const __half* __restrict__ feat,
                                          const float* __restrict__ sj_tab,
                                          int k0, int deg, float sib,
                                          int half, int sub, float* acc) {
#pragma unroll
    for (int r = 0; r < 8; r++) acc[r] = 0.f;
    int kend = k0 + deg;
#pragma unroll 8
    for (int k = k0 + half; k < kend; k += 2) {
        int s = g_sorted[k];
        float z = sib + sj_tab[s];
        float alpha = 1.0f / (1.0f + __expf(-z));
        uint4 raw = *((const uint4*)(feat + (size_t)s * HID) + sub);
        float2 f0 = __half22float2(*(__half2*)&raw.x);
        float2 f1 = __half22float2(*(__half2*)&raw.y);
        float2 f2 = __half22float2(*(__half2*)&raw.z);
        float2 f3 = __half22float2(*(__half2*)&raw.w);
        acc[0] += alpha * f0.x; acc[1] += alpha * f0.y;
        acc[2] += alpha * f1.x; acc[3] += alpha * f1.y;
        acc[4] += alpha * f2.x; acc[5] += alpha * f2.y;
        acc[6] += alpha * f3.x; acc[7] += alpha * f3.y;
    }
#pragma unroll
    for (int r = 0; r < 8; r++)
        acc[r] += __shfl_xor_sync(0xFFFFFFFFu, acc[r], 16);
}

// ---------------------------------------------------------------------------
// Layer 1 + fused layer-2 dots:
// g_hbh[d] = fp16(relu(acc/max(deg,1))); g_si2/g_sj2[d] from the rounded hb.
// ---------------------------------------------------------------------------
__global__ void agg1_kernel(const float* __restrict__ bptr,
                            const float* __restrict__ att2w, int n) {
    int d = (blockIdx.x * blockDim.x + threadIdx.x) >> 5;
    int lane = threadIdx.x & 31;
    if (d >= n) return;
    int half = lane >> 4, sub = lane & 15;
    float acc[8];
    float sib = g_si[d] + bptr[0];
    agg_accum(g_hh, g_sj, g_start[d], g_deg[d], sib, half, sub, acc);
    int deg = g_deg[d];
    float inv = 1.0f / (float)(deg < 1 ? 1 : deg);
    __half2 h01 = __floats2half2_rn(fmaxf(acc[0] * inv, 0.f), fmaxf(acc[1] * inv, 0.f));
    __half2 h23 = __floats2half2_rn(fmaxf(acc[2] * inv, 0.f), fmaxf(acc[3] * inv, 0.f));
    __half2 h45 = __floats2half2_rn(fmaxf(acc[4] * inv, 0.f), fmaxf(acc[5] * inv, 0.f));
    __half2 h67 = __floats2half2_rn(fmaxf(acc[6] * inv, 0.f), fmaxf(acc[7] * inv, 0.f));
    if (half == 0) {
        uint4 u;
        u.x = *(unsigned*)&h01; u.y = *(unsigned*)&h23;
        u.z = *(unsigned*)&h45; u.w = *(unsigned*)&h67;
        *((uint4*)(g_hbh + (size_t)d * HID) + sub) = u;
    }
    // fused layer-2 dots from the fp16-rounded values
    float f[8];
    float2 t;
    t = __half22float2(h01); f[0] = t.x; f[1] = t.y;
    t = __half22float2(h23); f[2] = t.x; f[3] = t.y;
    t = __half22float2(h45); f[4] = t.x; f[5] = t.y;
    t = __half22float2(h67); f[6] = t.x; f[7] = t.y;
    int j = sub * 8;
    float4 wi0 = *(const float4*)(att2w + j);
    float4 wi1 = *(const float4*)(att2w + j + 4);
    float4 wj0 = *(const float4*)(att2w + 128 + j);
    float4 wj1 = *(const float4*)(att2w + 128 + j + 4);
    float si = f[0]*wi0.x + f[1]*wi0.y + f[2]*wi0.z + f[3]*wi0.w
             + f[4]*wi1.x + f[5]*wi1.y + f[6]*wi1.z + f[7]*wi1.w;
    float sj = f[0]*wj0.x + f[1]*wj0.y + f[2]*wj0.z + f[3]*wj0.w
             + f[4]*wj1.x + f[5]*wj1.y + f[6]*wj1.z + f[7]*wj1.w;
    if (half) { si = 0.f; sj = 0.f; }
#pragma unroll
    for (int o = 16; o; o >>= 1) {
        si += __shfl_xor_sync(0xFFFFFFFFu, si, o);
        sj += __shfl_xor_sync(0xFFFFFFFFu, sj, o);
    }
    if (lane == 0) { g_si2[d] = si; g_sj2[d] = sj; }
}

// ---------------------------------------------------------------------------
// Layer 2 + classifier; restores the g_deg==0 invariant for graph replay.
// ---------------------------------------------------------------------------
__global__ void agg2_cls_kernel(const float* __restrict__ bptr,
                                const float* __restrict__ clsw,
                                const float* __restrict__ clsb,
                                float* __restrict__ out, int n) {
    int d = (blockIdx.x * blockDim.x + threadIdx.x) >> 5;
    int lane = threadIdx.x & 31;
    if (d >= n) return;
    int half = lane >> 4, sub = lane & 15;
    float acc[8];
    float sib = g_si2[d] + bptr[0];
    int deg = g_deg[d];
    if (lane == 0) g_deg[d] = 0;   // restore invariant for next replay
    agg_accum(g_hbh, g_sj2, g_start[d], deg, sib, half, sub, acc);
    float inv = 1.0f / (float)(deg < 1 ? 1 : deg);
    float o0 = 0.f, o1 = 0.f;
#pragma unroll
    for (int r = 0; r < 8; r++) {
        float v = acc[r] * inv;
        int j = sub * 8 + r;
        o0 += v * clsw[j * 2];
        o1 += v * clsw[j * 2 + 1];
    }
#pragma unroll
    for (int o = 8; o; o >>= 1) {
        o0 += __shfl_xor_sync(0xFFFFFFFFu, o0, o);
        o1 += __shfl_xor_sync(0xFFFFFFFFu, o1, o);
    }
    if (lane == 0) {
        out[(size_t)d * 2 + 0] = o0 + clsb[0];
        out[(size_t)d * 2 + 1] = o1 + clsb[1];
    }
}

// ---------------------------------------------------------------------------
extern "C" void kernel_launch(void* const* d_in, const int* in_sizes, int n_in,
                              void* d_out, int out_size) {
    const float* x      = (const float*)d_in[0];
    const int*   ei     = (const int*)  d_in[1];
    const float* enc_w  = (const float*)d_in[2];
    const float* enc_b  = (const float*)d_in[3];
    const float* att1_w = (const float*)d_in[4];
    const float* att1_b = (const float*)d_in[5];
    const float* att2_w = (const float*)d_in[6];
    const float* att2_b = (const float*)d_in[7];
    const float* cls_w  = (const float*)d_in[8];
    const float* cls_b  = (const float*)d_in[9];
    float* out = (float*)d_out;

    int N = in_sizes[0] / 256;
    int E = in_sizes[1] / 2;
    int nb = (N + 1023) / 1024;
    int Ggemm = (N + 127) / 128;
    int Gh = (E + 2047) / 2048;
    int Gd = (N + 7) / 8;

    // A: encoder GEMM (tensor cores) overlapped with dst histogram
    gemm_hist_kernel<<<Ggemm + Gh, 256>>>(x, enc_w, enc_b, ei, N, E, Ggemm);
    // CSR offsets
    scan_block_kernel<<<nb, 1024>>>(N);
    add_off_kernel<<<nb, 1024>>>(N, nb);
    // B: CSR scatter overlapped with layer-1 attention dots
    scatter_dots_kernel<<<Gh + Gd, 256>>>(ei, att1_w, E, N, Gh);
    // Layer 1 (+ fused layer-2 dots)
    agg1_kernel<<<Gd, 256>>>(att1_b, att2_w, N);
    // Layer 2 + classifier (+ deg invariant restore)
    agg2_cls_kernel<<<Gd, 256>>>(att2_b, cls_w, cls_b, out, N);
}

// round 13
// speedup vs baseline: 1.1496x; 1.0258x over previous
#include <cuda_runtime.h>
#include <cuda_fp16.h>
#include <cstdint>

#define HID 128
#define MAXN 50176
#define MAXE 1605632
#define SCAN_BLOCKS 64

__device__ __align__(16) __half g_hh [(size_t)MAXN * HID];  // layer-0 features (fp16)
__device__ __align__(16) __half g_hbh[(size_t)MAXN * HID];  // layer-1 features (fp16)
__device__ float g_si [MAXN];   // layer-1 attention scalars
__device__ float g_sj [MAXN];
__device__ float g_si2[MAXN];   // layer-2 attention scalars
__device__ float g_sj2[MAXN];
__device__ int   g_deg[MAXN];   // INVARIANT: all-zero at kernel_launch entry
__device__ int   g_start[MAXN];
__device__ int   g_cursor[MAXN];
__device__ int   g_sorted[MAXE];
__device__ int   g_bsum[SCAN_BLOCKS];

// ---------------------------------------------------------------------------
// Inline edge-dtype detection (per warp): odd int32 words of int64 data
// (values < 50000, little-endian) are all zero.
// ---------------------------------------------------------------------------
__device__ __forceinline__ int detect_is64(const int* __restrict__ p) {
    int lane = threadIdx.x & 31;
    unsigned v = 0;
#pragma unroll
    for (int j = 0; j < 4; j++)
        v |= (unsigned)p[2 * (lane * 4 + j) + 1];
    unsigned any = __ballot_sync(0xFFFFFFFFu, v != 0);
    return any == 0;
}

// ---------------------------------------------------------------------------
// GEMM helpers (fp16 mma, fp32 accum)
// ---------------------------------------------------------------------------
__device__ __forceinline__ void ldsm_x4(unsigned* a, uint32_t addr) {
    asm volatile("ldmatrix.sync.aligned.m8n8.x4.shared.b16 {%0,%1,%2,%3}, [%4];"
                 : "=r"(a[0]), "=r"(a[1]), "=r"(a[2]), "=r"(a[3]) : "r"(addr));
}
__device__ __forceinline__ void ldsm_x2_trans(unsigned* b, uint32_t addr) {
    asm volatile("ldmatrix.sync.aligned.m8n8.x2.trans.shared.b16 {%0,%1}, [%2];"
                 : "=r"(b[0]), "=r"(b[1]) : "r"(addr));
}
__device__ __forceinline__ void mma16816(float* c, const unsigned* a, const unsigned* b) {
    asm volatile("mma.sync.aligned.m16n8k16.row.col.f32.f16.f16.f32 "
                 "{%0,%1,%2,%3}, {%4,%5,%6,%7}, {%8,%9}, {%0,%1,%2,%3};"
                 : "+f"(c[0]), "+f"(c[1]), "+f"(c[2]), "+f"(c[3])
                 : "r"(a[0]), "r"(a[1]), "r"(a[2]), "r"(a[3]),
                   "r"(b[0]), "r"(b[1]));
}

// ---------------------------------------------------------------------------
// Mega-kernel A: blocks [0,Ggemm) = encoder GEMM; the rest = dst histogram.
// ---------------------------------------------------------------------------
__global__ void __launch_bounds__(256) gemm_hist_kernel(
        const float* __restrict__ A, const float* __restrict__ W,
        const float* __restrict__ bias, const int* __restrict__ ei,
        int M, int E, int Ggemm) {
    const int LDA = 40;
    const int LDB = 136;
    __shared__ __half As[128 * LDA];
    __shared__ __half Bs[32 * LDB];

    if (blockIdx.x >= Ggemm) {
        int is64 = detect_is64(ei);
        int base = (blockIdx.x - Ggemm) * 2048 + threadIdx.x;
#pragma unroll
        for (int i = 0; i < 8; i++) {
            int e = base + i * 256;
            if (e < E) {
                int d = is64 ? ei[2 * (E + e)] : ei[E + e];
                atomicAdd(&g_deg[d], 1);
            }
        }
        return;
    }

    int tid = threadIdx.x;
    int warp = tid >> 5;
    int lane = tid & 31;
    int warp_m = warp >> 2;
    int warp_n = warp & 3;
    int bm = blockIdx.x * 128;

    uint32_t sA = (uint32_t)__cvta_generic_to_shared(As);
    uint32_t sB = (uint32_t)__cvta_generic_to_shared(Bs);

    float c[4][4][4];
#pragma unroll
    for (int mt = 0; mt < 4; mt++)
#pragma unroll
        for (int nt = 0; nt < 4; nt++)
#pragma unroll
            for (int r = 0; r < 4; r++) c[mt][nt][r] = 0.f;

    for (int k0 = 0; k0 < 256; k0 += 32) {
#pragma unroll
        for (int i = 0; i < 4; i++) {
            int t = tid + i * 256;
            int r = t >> 3;
            int c4 = t & 7;
            int row = bm + r;
            float4 v = make_float4(0.f, 0.f, 0.f, 0.f);
            if (row < M)
                v = *(const float4*)(A + (size_t)row * 256 + k0 + c4 * 4);
            __half2 h01 = __floats2half2_rn(v.x, v.y);
            __half2 h23 = __floats2half2_rn(v.z, v.w);
            uint2 u = make_uint2(*(unsigned*)&h01, *(unsigned*)&h23);
            *(uint2*)(As + r * LDA + c4 * 4) = u;
        }
#pragma unroll
        for (int i = 0; i < 4; i++) {
            int t = tid + i * 256;
            int r = t >> 5;
            int c4 = t & 31;
            float4 v = *(const float4*)(W + (size_t)(k0 + r) * 128 + c4 * 4);
            __half2 h01 = __floats2half2_rn(v.x, v.y);
            __half2 h23 = __floats2half2_rn(v.z, v.w);
            uint2 u = make_uint2(*(unsigned*)&h01, *(unsigned*)&h23);
            *(uint2*)(Bs + r * LDB + c4 * 4) = u;
        }
        __syncthreads();
#pragma unroll
        for (int ks = 0; ks < 2; ks++) {
            int ko = ks * 16;
            unsigned a[4][4], b[4][2];
#pragma unroll
            for (int mt = 0; mt < 4; mt++) {
                uint32_t addr = sA + 2u * (uint32_t)((warp_m * 64 + mt * 16 + (lane & 15)) * LDA
                                           + ko + (lane >> 4) * 8);
                ldsm_x4(a[mt], addr);
            }
#pragma unroll
            for (int nt = 0; nt < 4; nt++) {
                uint32_t addr = sB + 2u * (uint32_t)((ko + (lane & 15)) * LDB
                                           + warp_n * 32 + nt * 8);
                ldsm_x2_trans(b[nt], addr);
            }
#pragma unroll
            for (int mt = 0; mt < 4; mt++)
#pragma unroll
                for (int nt = 0; nt < 4; nt++)
                    mma16816(c[mt][nt], a[mt], b[nt]);
        }
        __syncthreads();
    }

#pragma unroll
    for (int nt = 0; nt < 4; nt++) {
        int col = warp_n * 32 + nt * 8 + (lane & 3) * 2;
        float b0 = __ldg(bias + col);
        float b1 = __ldg(bias + col + 1);
#pragma unroll
        for (int mt = 0; mt < 4; mt++) {
            int row = bm + warp_m * 64 + mt * 16 + (lane >> 2);
            if (row < M) {
                float v0 = c[mt][nt][0] + b0;
                float v1 = c[mt][nt][1] + b1;
                __half2 h = __floats2half2_rn(v0 > 0.f ? v0 : 0.f,
                                              v1 > 0.f ? v1 : 0.f);
                *(__half2*)(g_hh + (size_t)row * HID + col) = h;
            }
            if (row + 8 < M) {
                float v0 = c[mt][nt][2] + b0;
                float v1 = c[mt][nt][3] + b1;
                __half2 h = __floats2half2_rn(v0 > 0.f ? v0 : 0.f,
                                              v1 > 0.f ? v1 : 0.f);
                *(__half2*)(g_hh + (size_t)(row + 8) * HID + col) = h;
            }
        }
    }
}

// ---------------------------------------------------------------------------
// CSR scan stages
// ---------------------------------------------------------------------------
__global__ void scan_block_kernel(int n) {
    __shared__ int warp_tot[32];
    int tid = threadIdx.x;
    int lane = tid & 31;
    int wid = tid >> 5;
    int i = blockIdx.x * 1024 + tid;
    int v = (i < n) ? g_deg[i] : 0;
    int x = v;
#pragma unroll
    for (int o = 1; o < 32; o <<= 1) {
        int y = __shfl_up_sync(0xFFFFFFFFu, x, o);
        if (lane >= o) x += y;
    }
    if (lane == 31) warp_tot[wid] = x;
    __syncthreads();
    if (wid == 0) {
        int t = warp_tot[lane];
#pragma unroll
        for (int o = 1; o < 32; o <<= 1) {
            int y = __shfl_up_sync(0xFFFFFFFFu, t, o);
            if (lane >= o) t += y;
        }
        warp_tot[lane] = t;
    }
    __syncthreads();
    int off = wid ? warp_tot[wid - 1] : 0;
    int incl = x + off;
    if (i < n) g_start[i] = incl - v;
    if (tid == 1023) g_bsum[blockIdx.x] = incl;
}

__global__ void add_off_kernel(int n, int nb) {
    __shared__ int boff_s;
    int tid = threadIdx.x;
    int b = blockIdx.x;
    if (tid < 32) {
        int acc = 0;
#pragma unroll
        for (int j = 0; j < 2; j++) {
            int idx = tid + j * 32;
            if (idx < b && idx < nb) acc += g_bsum[idx];
        }
#pragma unroll
        for (int o = 16; o; o >>= 1)
            acc += __shfl_xor_sync(0xFFFFFFFFu, acc, o);
        if (tid == 0) boff_s = acc;
    }
    __syncthreads();
    int i = b * 1024 + tid;
    if (i < n) {
        int s = g_start[i] + boff_s;
        g_start[i] = s;
        g_cursor[i] = s;
    }
}

// ---------------------------------------------------------------------------
// Mega-kernel B: blocks [0,Gs) = CSR scatter; rest = layer-1 dots.
// ---------------------------------------------------------------------------
__global__ void __launch_bounds__(256) scatter_dots_kernel(
        const int* __restrict__ ei, const float* __restrict__ w,
        int E, int n, int Gs) {
    if (blockIdx.x < Gs) {
        int is64 = detect_is64(ei);
        int base = blockIdx.x * 2048 + threadIdx.x;
#pragma unroll
        for (int i = 0; i < 8; i++) {
            int e = base + i * 256;
            if (e < E) {
                int s, d;
                if (is64) { s = ei[2 * e]; d = ei[2 * (E + e)]; }
                else      { s = ei[e];     d = ei[E + e]; }
                int pos = atomicAdd(&g_cursor[d], 1);
                g_sorted[pos] = s;
            }
        }
        return;
    }
    int node = (blockIdx.x - Gs) * 8 + (threadIdx.x >> 5);
    int lane = threadIdx.x & 31;
    if (node >= n) return;
    uint2 raw = *((const uint2*)(g_hh + (size_t)node * HID) + lane);
    float2 f01 = __half22float2(*(__half2*)&raw.x);
    float2 f23 = __half22float2(*(__half2*)&raw.y);
    float4 wi = ((const float4*)w)[lane];
    float4 wj = ((const float4*)w)[32 + lane];
    float si = f01.x * wi.x + f01.y * wi.y + f23.x * wi.z + f23.y * wi.w;
    float sj = f01.x * wj.x + f01.y * wj.y + f23.x * wj.z + f23.y * wj.w;
#pragma unroll
    for (int o = 16; o; o >>= 1) {
        si += __shfl_xor_sync(0xFFFFFFFFu, si, o);
        sj += __shfl_xor_sync(0xFFFFFFFFu, sj, o);
    }
    if (lane == 0) { g_si[node] = si; g_sj[node] = sj; }
}

// ---------------------------------------------------------------------------
// Gather-accumulate (R7 configuration, verified optimum): 2 edges per warp
// step, 16 lanes/edge, one uint4 (8-half) load per lane, unroll 4.
// After xor(16) ALL lanes hold full sums for features [sub*8, sub*8+8).
// ---------------------------------------------------------------------------
__device__ __forceinline__ void agg_accum(const __half* __restrict__ feat,
                                          const float* __restrict__ sj_tab,
                                          int k0, int deg, float sib,
                                          int half, int sub, float* acc) {
#pragma unroll
    for (int r = 0; r < 8; r++) acc[r] = 0.f;
    int kend = k0 + deg;
#pragma unroll 4
    for (int k = k0 + half; k < kend; k += 2) {
        int s = g_sorted[k];
        float z = sib + sj_tab[s];
        float alpha = 1.0f / (1.0f + __expf(-z));
        uint4 raw = *((const uint4*)(feat + (size_t)s * HID) + sub);
        float2 f0 = __half22float2(*(__half2*)&raw.x);
        float2 f1 = __half22float2(*(__half2*)&raw.y);
        float2 f2 = __half22float2(*(__half2*)&raw.z);
        float2 f3 = __half22float2(*(__half2*)&raw.w);
        acc[0] += alpha * f0.x; acc[1] += alpha * f0.y;
        acc[2] += alpha * f1.x; acc[3] += alpha * f1.y;
        acc[4] += alpha * f2.x; acc[5] += alpha * f2.y;
        acc[6] += alpha * f3.x; acc[7] += alpha * f3.y;
    }
#pragma unroll
    for (int r = 0; r < 8; r++)
        acc[r] += __shfl_xor_sync(0xFFFFFFFFu, acc[r], 16);
}

// ---------------------------------------------------------------------------
// Layer 1 + fused layer-2 dots:
// g_hbh[d] = fp16(relu(acc/max(deg,1))); g_si2/g_sj2[d] from the rounded hb.
// ---------------------------------------------------------------------------
__global__ void agg1_kernel(const float* __restrict__ bptr,
                            const float* __restrict__ att2w, int n) {
    int d = (blockIdx.x * blockDim.x + threadIdx.x) >> 5;
    int lane = threadIdx.x & 31;
    if (d >= n) return;
    int half = lane >> 4, sub = lane & 15;
    float acc[8];
    float sib = g_si[d] + bptr[0];
    int deg = g_deg[d];
    agg_accum(g_hh, g_sj, g_start[d], deg, sib, half, sub, acc);
    float inv = 1.0f / (float)(deg < 1 ? 1 : deg);
    __half2 h01 = __floats2half2_rn(fmaxf(acc[0] * inv, 0.f), fmaxf(acc[1] * inv, 0.f));
    __half2 h23 = __floats2half2_rn(fmaxf(acc[2] * inv, 0.f), fmaxf(acc[3] * inv, 0.f));
    __half2 h45 = __floats2half2_rn(fmaxf(acc[4] * inv, 0.f), fmaxf(acc[5] * inv, 0.f));
    __half2 h67 = __floats2half2_rn(fmaxf(acc[6] * inv, 0.f), fmaxf(acc[7] * inv, 0.f));
    if (half == 0) {
        uint4 u;
        u.x = *(unsigned*)&h01; u.y = *(unsigned*)&h23;
        u.z = *(unsigned*)&h45; u.w = *(unsigned*)&h67;
        *((uint4*)(g_hbh + (size_t)d * HID) + sub) = u;
    }
    // fused layer-2 dots from the fp16-rounded values
    float f[8];
    float2 t;
    t = __half22float2(h01); f[0] = t.x; f[1] = t.y;
    t = __half22float2(h23); f[2] = t.x; f[3] = t.y;
    t = __half22float2(h45); f[4] = t.x; f[5] = t.y;
    t = __half22float2(h67); f[6] = t.x; f[7] = t.y;
    int j = sub * 8;
    float4 wi0 = *(const float4*)(att2w + j);
    float4 wi1 = *(const float4*)(att2w + j + 4);
    float4 wj0 = *(const float4*)(att2w + 128 + j);
    float4 wj1 = *(const float4*)(att2w + 128 + j + 4);
    float si = f[0]*wi0.x + f[1]*wi0.y + f[2]*wi0.z + f[3]*wi0.w
             + f[4]*wi1.x + f[5]*wi1.y + f[6]*wi1.z + f[7]*wi1.w;
    float sj = f[0]*wj0.x + f[1]*wj0.y + f[2]*wj0.z + f[3]*wj0.w
             + f[4]*wj1.x + f[5]*wj1.y + f[6]*wj1.z + f[7]*wj1.w;
    if (half) { si = 0.f; sj = 0.f; }
#pragma unroll
    for (int o = 16; o; o >>= 1) {
        si += __shfl_xor_sync(0xFFFFFFFFu, si, o);
        sj += __shfl_xor_sync(0xFFFFFFFFu, sj, o);
    }
    if (lane == 0) { g_si2[d] = si; g_sj2[d] = sj; }
}

// ---------------------------------------------------------------------------
// Layer 2 + classifier; restores the g_deg==0 invariant for graph replay.
// ---------------------------------------------------------------------------
__global__ void agg2_cls_kernel(const float* __restrict__ bptr,
                                const float* __restrict__ clsw,
                                const float* __restrict__ clsb,
                                float* __restrict__ out, int n) {
    int d = (blockIdx.x * blockDim.x + threadIdx.x) >> 5;
    int lane = threadIdx.x & 31;
    if (d >= n) return;
    int half = lane >> 4, sub = lane & 15;
    float acc[8];
    float sib = g_si2[d] + bptr[0];
    int deg = g_deg[d];
    if (lane == 0) g_deg[d] = 0;   // restore invariant for next replay
    agg_accum(g_hbh, g_sj2, g_start[d], deg, sib, half, sub, acc);
    float inv = 1.0f / (float)(deg < 1 ? 1 : deg);
    float o0 = 0.f, o1 = 0.f;
#pragma unroll
    for (int r = 0; r < 8; r++) {
        float v = acc[r] * inv;
        int j = sub * 8 + r;
        o0 += v * clsw[j * 2];
        o1 += v * clsw[j * 2 + 1];
    }
#pragma unroll
    for (int o = 8; o; o >>= 1) {
        o0 += __shfl_xor_sync(0xFFFFFFFFu, o0, o);
        o1 += __shfl_xor_sync(0xFFFFFFFFu, o1, o);
    }
    if (lane == 0) {
        out[(size_t)d * 2 + 0] = o0 + clsb[0];
        out[(size_t)d * 2 + 1] = o1 + clsb[1];
    }
}

// ---------------------------------------------------------------------------
extern "C" void kernel_launch(void* const* d_in, const int* in_sizes, int n_in,
                              void* d_out, int out_size) {
    const float* x      = (const float*)d_in[0];
    const int*   ei     = (const int*)  d_in[1];
    const float* enc_w  = (const float*)d_in[2];
    const float* enc_b  = (const float*)d_in[3];
    const float* att1_w = (const float*)d_in[4];
    const float* att1_b = (const float*)d_in[5];
    const float* att2_w = (const float*)d_in[6];
    const float* att2_b = (const float*)d_in[7];
    const float* cls_w  = (const float*)d_in[8];
    const float* cls_b  = (const float*)d_in[9];
    float* out = (float*)d_out;

    int N = in_sizes[0] / 256;
    int E = in_sizes[1] / 2;
    int nb = (N + 1023) / 1024;
    int Ggemm = (N + 127) / 128;
    int Gh = (E + 2047) / 2048;
    int Gd = (N + 7) / 8;

    // A: encoder GEMM (tensor cores) overlapped with dst histogram
    gemm_hist_kernel<<<Ggemm + Gh, 256>>>(x, enc_w, enc_b, ei, N, E, Ggemm);
    // CSR offsets
    scan_block_kernel<<<nb, 1024>>>(N);
    add_off_kernel<<<nb, 1024>>>(N, nb);
    // B: CSR scatter overlapped with layer-1 attention dots
    scatter_dots_kernel<<<Gh + Gd, 256>>>(ei, att1_w, E, N, Gh);
    // Layer 1 (+ fused layer-2 dots)
    agg1_kernel<<<Gd, 256>>>(att1_b, att2_w, N);
    // Layer 2 + classifier (+ deg invariant restore)
    agg2_cls_kernel<<<Gd, 256>>>(att2_b, cls_w, cls_b, out, N);
}

// round 14
// speedup vs baseline: 1.3790x; 1.1996x over previous
#include <cuda_runtime.h>
#include <cuda_fp16.h>
#include <cstdint>

#define HID 128
#define MAXN 50176
#define MAXE 1605632
#define SCAN_BLOCKS 64

__device__ __align__(16) __half g_hh [(size_t)MAXN * HID];  // layer-0 features (fp16)
__device__ __align__(16) __half g_hbh[(size_t)MAXN * HID];  // layer-1 features (fp16)
__device__ float g_si [MAXN];   // layer-1 attention scalars
__device__ float g_sj [MAXN];
__device__ float g_si2[MAXN];   // layer-2 attention scalars
__device__ float g_sj2[MAXN];
__device__ int   g_deg[MAXN];   // INVARIANT: all-zero at kernel_launch entry
__device__ int   g_start[MAXN];
__device__ int   g_cursor[MAXN];
__device__ int   g_sorted[MAXE];
__device__ int   g_bsum[SCAN_BLOCKS];

// ---------------------------------------------------------------------------
// Inline edge-dtype detection (per warp, no global state):
// samples odd int32 words 1,3,...,255. int64 (values<50000) -> all zero.
// ---------------------------------------------------------------------------
__device__ __forceinline__ int detect_is64(const int* __restrict__ p) {
    int lane = threadIdx.x & 31;
    unsigned v = 0;
#pragma unroll
    for (int j = 0; j < 4; j++)
        v |= (unsigned)p[2 * (lane * 4 + j) + 1];
    unsigned any = __ballot_sync(0xFFFFFFFFu, v != 0);
    return any == 0;
}

// ---------------------------------------------------------------------------
// GEMM helpers (fp16 mma, fp32 accum)
// ---------------------------------------------------------------------------
__device__ __forceinline__ void ldsm_x4(unsigned* a, uint32_t addr) {
    asm volatile("ldmatrix.sync.aligned.m8n8.x4.shared.b16 {%0,%1,%2,%3}, [%4];"
                 : "=r"(a[0]), "=r"(a[1]), "=r"(a[2]), "=r"(a[3]) : "r"(addr));
}
__device__ __forceinline__ void ldsm_x2_trans(unsigned* b, uint32_t addr) {
    asm volatile("ldmatrix.sync.aligned.m8n8.x2.trans.shared.b16 {%0,%1}, [%2];"
                 : "=r"(b[0]), "=r"(b[1]) : "r"(addr));
}
__device__ __forceinline__ void mma16816(float* c, const unsigned* a, const unsigned* b) {
    asm volatile("mma.sync.aligned.m16n8k16.row.col.f32.f16.f16.f32 "
                 "{%0,%1,%2,%3}, {%4,%5,%6,%7}, {%8,%9}, {%0,%1,%2,%3};"
                 : "+f"(c[0]), "+f"(c[1]), "+f"(c[2]), "+f"(c[3])
                 : "r"(a[0]), "r"(a[1]), "r"(a[2]), "r"(a[3]),
                   "r"(b[0]), "r"(b[1]));
}

// ---------------------------------------------------------------------------
// Mega-kernel A: blocks [0,Ggemm) do encoder GEMM tiles; the rest do the
// dst-degree histogram (edge decode inline).
// ---------------------------------------------------------------------------
__global__ void __launch_bounds__(256) gemm_hist_kernel(
        const float* __restrict__ A, const float* __restrict__ W,
        const float* __restrict__ bias, const int* __restrict__ ei,
        int M, int E, int Ggemm) {
    const int LDA = 40;
    const int LDB = 136;
    __shared__ __half As[128 * LDA];
    __shared__ __half Bs[32 * LDB];

    if (blockIdx.x >= Ggemm) {
        // ---- histogram path ----
        int is64 = detect_is64(ei);
        int base = (blockIdx.x - Ggemm) * 2048 + threadIdx.x;
#pragma unroll
        for (int i = 0; i < 8; i++) {
            int e = base + i * 256;
            if (e < E) {
                int d = is64 ? ei[2 * (E + e)] : ei[E + e];
                atomicAdd(&g_deg[d], 1);
            }
        }
        return;
    }

    // ---- GEMM path ----
    int tid = threadIdx.x;
    int warp = tid >> 5;
    int lane = tid & 31;
    int warp_m = warp >> 2;
    int warp_n = warp & 3;
    int bm = blockIdx.x * 128;

    uint32_t sA = (uint32_t)__cvta_generic_to_shared(As);
    uint32_t sB = (uint32_t)__cvta_generic_to_shared(Bs);

    float c[4][4][4];
#pragma unroll
    for (int mt = 0; mt < 4; mt++)
#pragma unroll
        for (int nt = 0; nt < 4; nt++)
#pragma unroll
            for (int r = 0; r < 4; r++) c[mt][nt][r] = 0.f;

    for (int k0 = 0; k0 < 256; k0 += 32) {
#pragma unroll
        for (int i = 0; i < 4; i++) {
            int t = tid + i * 256;
            int r = t >> 3;
            int c4 = t & 7;
            int row = bm + r;
            float4 v = make_float4(0.f, 0.f, 0.f, 0.f);
            if (row < M)
                v = *(const float4*)(A + (size_t)row * 256 + k0 + c4 * 4);
            __half2 h01 = __floats2half2_rn(v.x, v.y);
            __half2 h23 = __floats2half2_rn(v.z, v.w);
            uint2 u = make_uint2(*(unsigned*)&h01, *(unsigned*)&h23);
            *(uint2*)(As + r * LDA + c4 * 4) = u;
        }
#pragma unroll
        for (int i = 0; i < 4; i++) {
            int t = tid + i * 256;
            int r = t >> 5;
            int c4 = t & 31;
            float4 v = *(const float4*)(W + (size_t)(k0 + r) * 128 + c4 * 4);
            __half2 h01 = __floats2half2_rn(v.x, v.y);
            __half2 h23 = __floats2half2_rn(v.z, v.w);
            uint2 u = make_uint2(*(unsigned*)&h01, *(unsigned*)&h23);
            *(uint2*)(Bs + r * LDB + c4 * 4) = u;
        }
        __syncthreads();
#pragma unroll
        for (int ks = 0; ks < 2; ks++) {
            int ko = ks * 16;
            unsigned a[4][4], b[4][2];
#pragma unroll
            for (int mt = 0; mt < 4; mt++) {
                uint32_t addr = sA + 2u * (uint32_t)((warp_m * 64 + mt * 16 + (lane & 15)) * LDA
                                           + ko + (lane >> 4) * 8);
                ldsm_x4(a[mt], addr);
            }
#pragma unroll
            for (int nt = 0; nt < 4; nt++) {
                uint32_t addr = sB + 2u * (uint32_t)((ko + (lane & 15)) * LDB
                                           + warp_n * 32 + nt * 8);
                ldsm_x2_trans(b[nt], addr);
            }
#pragma unroll
            for (int mt = 0; mt < 4; mt++)
#pragma unroll
                for (int nt = 0; nt < 4; nt++)
                    mma16816(c[mt][nt], a[mt], b[nt]);
        }
        __syncthreads();
    }

#pragma unroll
    for (int nt = 0; nt < 4; nt++) {
        int col = warp_n * 32 + nt * 8 + (lane & 3) * 2;
        float b0 = __ldg(bias + col);
        float b1 = __ldg(bias + col + 1);
#pragma unroll
        for (int mt = 0; mt < 4; mt++) {
            int row = bm + warp_m * 64 + mt * 16 + (lane >> 2);
            if (row < M) {
                float v0 = c[mt][nt][0] + b0;
                float v1 = c[mt][nt][1] + b1;
                __half2 h = __floats2half2_rn(v0 > 0.f ? v0 : 0.f,
                                              v1 > 0.f ? v1 : 0.f);
                *(__half2*)(g_hh + (size_t)row * HID + col) = h;
            }
            if (row + 8 < M) {
                float v0 = c[mt][nt][2] + b0;
                float v1 = c[mt][nt][3] + b1;
                __half2 h = __floats2half2_rn(v0 > 0.f ? v0 : 0.f,
                                              v1 > 0.f ? v1 : 0.f);
                *(__half2*)(g_hh + (size_t)(row + 8) * HID + col) = h;
            }
        }
    }
}

// ---------------------------------------------------------------------------
// CSR scan stages
// ---------------------------------------------------------------------------
__global__ void scan_block_kernel(int n) {
    __shared__ int warp_tot[32];
    int tid = threadIdx.x;
    int lane = tid & 31;
    int wid = tid >> 5;
    int i = blockIdx.x * 1024 + tid;
    int v = (i < n) ? g_deg[i] : 0;
    int x = v;
#pragma unroll
    for (int o = 1; o < 32; o <<= 1) {
        int y = __shfl_up_sync(0xFFFFFFFFu, x, o);
        if (lane >= o) x += y;
    }
    if (lane == 31) warp_tot[wid] = x;
    __syncthreads();
    if (wid == 0) {
        int t = warp_tot[lane];
#pragma unroll
        for (int o = 1; o < 32; o <<= 1) {
            int y = __shfl_up_sync(0xFFFFFFFFu, t, o);
            if (lane >= o) t += y;
        }
        warp_tot[lane] = t;
    }
    __syncthreads();
    int off = wid ? warp_tot[wid - 1] : 0;
    int incl = x + off;
    if (i < n) g_start[i] = incl - v;
    if (tid == 1023) g_bsum[blockIdx.x] = incl;
}

__global__ void add_off_kernel(int n, int nb) {
    __shared__ int boff_s;
    int tid = threadIdx.x;
    int b = blockIdx.x;
    if (tid < 32) {
        int acc = 0;
#pragma unroll
        for (int j = 0; j < 2; j++) {
            int idx = tid + j * 32;
            if (idx < b && idx < nb) acc += g_bsum[idx];
        }
#pragma unroll
        for (int o = 16; o; o >>= 1)
            acc += __shfl_xor_sync(0xFFFFFFFFu, acc, o);
        if (tid == 0) boff_s = acc;
    }
    __syncthreads();
    int i = b * 1024 + tid;
    if (i < n) {
        int s = g_start[i] + boff_s;
        g_start[i] = s;
        g_cursor[i] = s;
    }
}

// ---------------------------------------------------------------------------
// Mega-kernel B: blocks [0,Gs) do CSR scatter; the rest do layer-1 dots
// (si = h.w[:128], sj = h.w[128:], one warp per node).
// ---------------------------------------------------------------------------
__global__ void __launch_bounds__(256) scatter_dots_kernel(
        const int* __restrict__ ei, const float* __restrict__ w,
        int E, int n, int Gs) {
    if (blockIdx.x < Gs) {
        int is64 = detect_is64(ei);
        int base = blockIdx.x * 2048 + threadIdx.x;
#pragma unroll
        for (int i = 0; i < 8; i++) {
            int e = base + i * 256;
            if (e < E) {
                int s, d;
                if (is64) { s = ei[2 * e]; d = ei[2 * (E + e)]; }
                else      { s = ei[e];     d = ei[E + e]; }
                int pos = atomicAdd(&g_cursor[d], 1);
                g_sorted[pos] = s;
            }
        }
        return;
    }
    int node = (blockIdx.x - Gs) * 8 + (threadIdx.x >> 5);
    int lane = threadIdx.x & 31;
    if (node >= n) return;
    uint2 raw = *((const uint2*)(g_hh + (size_t)node * HID) + lane);
    float2 f01 = __half22float2(*(__half2*)&raw.x);
    float2 f23 = __half22float2(*(__half2*)&raw.y);
    float4 wi = ((const float4*)w)[lane];
    float4 wj = ((const float4*)w)[32 + lane];
    float si = f01.x * wi.x + f01.y * wi.y + f23.x * wi.z + f23.y * wi.w;
    float sj = f01.x * wj.x + f01.y * wj.y + f23.x * wj.z + f23.y * wj.w;
#pragma unroll
    for (int o = 16; o; o >>= 1) {
        si += __shfl_xor_sync(0xFFFFFFFFu, si, o);
        sj += __shfl_xor_sync(0xFFFFFFFFu, sj, o);
    }
    if (lane == 0) { g_si[node] = si; g_sj[node] = sj; }
}

// ---------------------------------------------------------------------------
// Shared gather-accumulate: 2 edges per warp step, 16 lanes/edge, uint4 loads.
// After the xor(16) combine ALL lanes hold the full sums for features
// [sub*8, sub*8+8), sub = lane&15.
// ---------------------------------------------------------------------------
__device__ __forceinline__ void agg_accum(const __half* __restrict__ feat,
                                          const float* __restrict__ sj_tab,
                                          int k0, int deg, float sib,
                                          int half, int sub, float* acc) {
#pragma unroll
    for (int r = 0; r < 8; r++) acc[r] = 0.f;
    int kend = k0 + deg;
#pragma unroll 4
    for (int k = k0 + half; k < kend; k += 2) {
        int s = g_sorted[k];
        float z = sib + sj_tab[s];
        float alpha = 1.0f / (1.0f + __expf(-z));
        uint4 raw = *((const uint4*)(feat + (size_t)s * HID) + sub);
        float2 f0 = __half22float2(*(__half2*)&raw.x);
        float2 f1 = __half22float2(*(__half2*)&raw.y);
        float2 f2 = __half22float2(*(__half2*)&raw.z);
        float2 f3 = __half22float2(*(__half2*)&raw.w);
        acc[0] += alpha * f0.x; acc[1] += alpha * f0.y;
        acc[2] += alpha * f1.x; acc[3] += alpha * f1.y;
        acc[4] += alpha * f2.x; acc[5] += alpha * f2.y;
        acc[6] += alpha * f3.x; acc[7] += alpha * f3.y;
    }
#pragma unroll
    for (int r = 0; r < 8; r++)
        acc[r] += __shfl_xor_sync(0xFFFFFFFFu, acc[r], 16);
}

// ---------------------------------------------------------------------------
// Layer 1 + fused layer-2 dots:
// g_hbh[d] = fp16(relu(acc/max(deg,1))); g_si2/g_sj2[d] = hb . att2_w halves.
// ---------------------------------------------------------------------------
__global__ void agg1_kernel(const float* __restrict__ bptr,
                            const float* __restrict__ att2w, int n) {
    int d = (blockIdx.x * blockDim.x + threadIdx.x) >> 5;
    int lane = threadIdx.x & 31;
    if (d >= n) return;
    int half = lane >> 4, sub = lane & 15;
    float acc[8];
    float sib = g_si[d] + bptr[0];
    agg_accum(g_hh, g_sj, g_start[d], g_deg[d], sib, half, sub, acc);
    int deg = g_deg[d];
    float inv = 1.0f / (float)(deg < 1 ? 1 : deg);
    __half2 h01 = __floats2half2_rn(fmaxf(acc[0] * inv, 0.f), fmaxf(acc[1] * inv, 0.f));
    __half2 h23 = __floats2half2_rn(fmaxf(acc[2] * inv, 0.f), fmaxf(acc[3] * inv, 0.f));
    __half2 h45 = __floats2half2_rn(fmaxf(acc[4] * inv, 0.f), fmaxf(acc[5] * inv, 0.f));
    __half2 h67 = __floats2half2_rn(fmaxf(acc[6] * inv, 0.f), fmaxf(acc[7] * inv, 0.f));
    if (half == 0) {
        uint4 u;
        u.x = *(unsigned*)&h01; u.y = *(unsigned*)&h23;
        u.z = *(unsigned*)&h45; u.w = *(unsigned*)&h67;
        *((uint4*)(g_hbh + (size_t)d * HID) + sub) = u;
    }
    // fused layer-2 dots from the fp16-rounded values
    float f[8];
    float2 t;
    t = __half22float2(h01); f[0] = t.x; f[1] = t.y;
    t = __half22float2(h23); f[2] = t.x; f[3] = t.y;
    t = __half22float2(h45); f[4] = t.x; f[5] = t.y;
    t = __half22float2(h67); f[6] = t.x; f[7] = t.y;
    int j = sub * 8;
    float4 wi0 = *(const float4*)(att2w + j);
    float4 wi1 = *(const float4*)(att2w + j + 4);
    float4 wj0 = *(const float4*)(att2w + 128 + j);
    float4 wj1 = *(const float4*)(att2w + 128 + j + 4);
    float si = f[0]*wi0.x + f[1]*wi0.y + f[2]*wi0.z + f[3]*wi0.w
             + f[4]*wi1.x + f[5]*wi1.y + f[6]*wi1.z + f[7]*wi1.w;
    float sj = f[0]*wj0.x + f[1]*wj0.y + f[2]*wj0.z + f[3]*wj0.w
             + f[4]*wj1.x + f[5]*wj1.y + f[6]*wj1.z + f[7]*wj1.w;
    if (half) { si = 0.f; sj = 0.f; }
#pragma unroll
    for (int o = 16; o; o >>= 1) {
        si += __shfl_xor_sync(0xFFFFFFFFu, si, o);
        sj += __shfl_xor_sync(0xFFFFFFFFu, sj, o);
    }
    if (lane == 0) { g_si2[d] = si; g_sj2[d] = sj; }
}

// ---------------------------------------------------------------------------
// Layer 2 + classifier; restores g_deg invariant (zeroes it after last use).
// ---------------------------------------------------------------------------
__global__ void agg2_cls_kernel(const float* __restrict__ bptr,
                                const float* __restrict__ clsw,
                                const float* __restrict__ clsb,
                                float* __restrict__ out, int n) {
    int d = (blockIdx.x * blockDim.x + threadIdx.x) >> 5;
    int lane = threadIdx.x & 31;
    if (d >= n) return;
    int half = lane >> 4, sub = lane & 15;
    float acc[8];
    float sib = g_si2[d] + bptr[0];
    agg_accum(g_hbh, g_sj2, g_start[d], g_deg[d], sib, half, sub, acc);
    int deg = g_deg[d];
    if (lane == 0) g_deg[d] = 0;   // restore invariant for next replay
    float inv = 1.0f / (float)(deg < 1 ? 1 : deg);
    float o0 = 0.f, o1 = 0.f;
#pragma unroll
    for (int r = 0; r < 8; r++) {
        float v = acc[r] * inv;
        int j = sub * 8 + r;
        o0 += v * clsw[j * 2];
        o1 += v * clsw[j * 2 + 1];
    }
#pragma unroll
    for (int o = 8; o; o >>= 1) {
        o0 += __shfl_xor_sync(0xFFFFFFFFu, o0, o);
        o1 += __shfl_xor_sync(0xFFFFFFFFu, o1, o);
    }
    if (lane == 0) {
        out[(size_t)d * 2 + 0] = o0 + clsb[0];
        out[(size_t)d * 2 + 1] = o1 + clsb[1];
    }
}

// ---------------------------------------------------------------------------
extern "C" void kernel_launch(void* const* d_in, const int* in_sizes, int n_in,
                              void* d_out, int out_size) {
    const float* x      = (const float*)d_in[0];
    const int*   ei     = (const int*)  d_in[1];
    const float* enc_w  = (const float*)d_in[2];
    const float* enc_b  = (const float*)d_in[3];
    const float* att1_w = (const float*)d_in[4];
    const float* att1_b = (const float*)d_in[5];
    const float* att2_w = (const float*)d_in[6];
    const float* att2_b = (const float*)d_in[7];
    const float* cls_w  = (const float*)d_in[8];
    const float* cls_b  = (const float*)d_in[9];
    float* out = (float*)d_out;

    int N = in_sizes[0] / 256;
    int E = in_sizes[1] / 2;
    int nb = (N + 1023) / 1024;
    int Ggemm = (N + 127) / 128;
    int Gh = (E + 2047) / 2048;
    int Gd = (N + 7) / 8;

    // A: encoder GEMM (tensor cores) overlapped with dst histogram
    gemm_hist_kernel<<<Ggemm + Gh, 256>>>(x, enc_w, enc_b, ei, N, E, Ggemm);
    // CSR offsets
    scan_block_kernel<<<nb, 1024>>>(N);
    add_off_kernel<<<nb, 1024>>>(N, nb);
    // B: CSR scatter overlapped with layer-1 attention dots
    scatter_dots_kernel<<<Gh + Gd, 256>>>(ei, att1_w, E, N, Gh);
    // Layer 1 (+ fused layer-2 dots)
    agg1_kernel<<<Gd, 256>>>(att1_b, att2_w, N);
    // Layer 2 + classifier (+ deg invariant restore)
    agg2_cls_kernel<<<Gd, 256>>>(att2_b, cls_w, cls_b, out, N);
}

// round 15
// speedup vs baseline: 1.4423x; 1.0459x over previous
#include <cuda_runtime.h>
#include <cuda_fp16.h>
#include <cstdint>

#define HID 128
#define MAXN 50176
#define MAXE 1605632
#define SCAN_BLOCKS 64

__device__ __align__(16) __half g_hh [(size_t)MAXN * HID];  // layer-0 features (fp16)
__device__ __align__(16) __half g_hbh[(size_t)MAXN * HID];  // layer-1 features (fp16)
__device__ float g_si [MAXN];   // layer-1 attention scalars
__device__ float g_sj [MAXN];
__device__ float g_si2[MAXN];   // layer-2 attention scalars
__device__ float g_sj2[MAXN];
__device__ int   g_deg[MAXN];   // INVARIANT: all-zero at kernel_launch entry
__device__ int   g_start[MAXN];
__device__ int   g_cursor[MAXN];
__device__ int   g_sorted[MAXE];
__device__ int   g_bsum[SCAN_BLOCKS];

// ---------------------------------------------------------------------------
// Inline edge-dtype detection (per warp, no global state):
// samples odd int32 words 1,3,...,255. int64 (values<50000) -> all zero.
// ---------------------------------------------------------------------------
__device__ __forceinline__ int detect_is64(const int* __restrict__ p) {
    int lane = threadIdx.x & 31;
    unsigned v = 0;
#pragma unroll
    for (int j = 0; j < 4; j++)
        v |= (unsigned)p[2 * (lane * 4 + j) + 1];
    unsigned any = __ballot_sync(0xFFFFFFFFu, v != 0);
    return any == 0;
}

// ---------------------------------------------------------------------------
// GEMM helpers (fp16 mma, fp32 accum)
// ---------------------------------------------------------------------------
__device__ __forceinline__ void ldsm_x4(unsigned* a, uint32_t addr) {
    asm volatile("ldmatrix.sync.aligned.m8n8.x4.shared.b16 {%0,%1,%2,%3}, [%4];"
                 : "=r"(a[0]), "=r"(a[1]), "=r"(a[2]), "=r"(a[3]) : "r"(addr));
}
__device__ __forceinline__ void ldsm_x2_trans(unsigned* b, uint32_t addr) {
    asm volatile("ldmatrix.sync.aligned.m8n8.x2.trans.shared.b16 {%0,%1}, [%2];"
                 : "=r"(b[0]), "=r"(b[1]) : "r"(addr));
}
__device__ __forceinline__ void mma16816(float* c, const unsigned* a, const unsigned* b) {
    asm volatile("mma.sync.aligned.m16n8k16.row.col.f32.f16.f16.f32 "
                 "{%0,%1,%2,%3}, {%4,%5,%6,%7}, {%8,%9}, {%0,%1,%2,%3};"
                 : "+f"(c[0]), "+f"(c[1]), "+f"(c[2]), "+f"(c[3])
                 : "r"(a[0]), "r"(a[1]), "r"(a[2]), "r"(a[3]),
                   "r"(b[0]), "r"(b[1]));
}

// Feature gather load: 128-bit, non-coherent, L1 no-allocate (preserve L1 for
// the small sj table / sorted stream; feature table is 12.8 MB random -> ~0%
// L1 hit rate, allocation is pure thrash).
__device__ __forceinline__ uint4 ldg_na_v4(const uint4* p) {
    uint4 v;
    asm("ld.global.nc.L1::no_allocate.v4.u32 {%0,%1,%2,%3}, [%4];"
        : "=r"(v.x), "=r"(v.y), "=r"(v.z), "=r"(v.w) : "l"(p));
    return v;
}

// ---------------------------------------------------------------------------
// Mega-kernel A: blocks [0,Ggemm) do encoder GEMM tiles; the rest do the
// dst-degree histogram (edge decode inline).
// ---------------------------------------------------------------------------
__global__ void __launch_bounds__(256) gemm_hist_kernel(
        const float* __restrict__ A, const float* __restrict__ W,
        const float* __restrict__ bias, const int* __restrict__ ei,
        int M, int E, int Ggemm) {
    const int LDA = 40;
    const int LDB = 136;
    __shared__ __half As[128 * LDA];
    __shared__ __half Bs[32 * LDB];

    if (blockIdx.x >= Ggemm) {
        // ---- histogram path ----
        int is64 = detect_is64(ei);
        int base = (blockIdx.x - Ggemm) * 2048 + threadIdx.x;
#pragma unroll
        for (int i = 0; i < 8; i++) {
            int e = base + i * 256;
            if (e < E) {
                int d = is64 ? ei[2 * (E + e)] : ei[E + e];
                atomicAdd(&g_deg[d], 1);
            }
        }
        return;
    }

    // ---- GEMM path ----
    int tid = threadIdx.x;
    int warp = tid >> 5;
    int lane = tid & 31;
    int warp_m = warp >> 2;
    int warp_n = warp & 3;
    int bm = blockIdx.x * 128;

    uint32_t sA = (uint32_t)__cvta_generic_to_shared(As);
    uint32_t sB = (uint32_t)__cvta_generic_to_shared(Bs);

    float c[4][4][4];
#pragma unroll
    for (int mt = 0; mt < 4; mt++)
#pragma unroll
        for (int nt = 0; nt < 4; nt++)
#pragma unroll
            for (int r = 0; r < 4; r++) c[mt][nt][r] = 0.f;

    for (int k0 = 0; k0 < 256; k0 += 32) {
#pragma unroll
        for (int i = 0; i < 4; i++) {
            int t = tid + i * 256;
            int r = t >> 3;
            int c4 = t & 7;
            int row = bm + r;
            float4 v = make_float4(0.f, 0.f, 0.f, 0.f);
            if (row < M)
                v = *(const float4*)(A + (size_t)row * 256 + k0 + c4 * 4);
            __half2 h01 = __floats2half2_rn(v.x, v.y);
            __half2 h23 = __floats2half2_rn(v.z, v.w);
            uint2 u = make_uint2(*(unsigned*)&h01, *(unsigned*)&h23);
            *(uint2*)(As + r * LDA + c4 * 4) = u;
        }
#pragma unroll
        for (int i = 0; i < 4; i++) {
            int t = tid + i * 256;
            int r = t >> 5;
            int c4 = t & 31;
            float4 v = *(const float4*)(W + (size_t)(k0 + r) * 128 + c4 * 4);
            __half2 h01 = __floats2half2_rn(v.x, v.y);
            __half2 h23 = __floats2half2_rn(v.z, v.w);
            uint2 u = make_uint2(*(unsigned*)&h01, *(unsigned*)&h23);
            *(uint2*)(Bs + r * LDB + c4 * 4) = u;
        }
        __syncthreads();
#pragma unroll
        for (int ks = 0; ks < 2; ks++) {
            int ko = ks * 16;
            unsigned a[4][4], b[4][2];
#pragma unroll
            for (int mt = 0; mt < 4; mt++) {
                uint32_t addr = sA + 2u * (uint32_t)((warp_m * 64 + mt * 16 + (lane & 15)) * LDA
                                           + ko + (lane >> 4) * 8);
                ldsm_x4(a[mt], addr);
            }
#pragma unroll
            for (int nt = 0; nt < 4; nt++) {
                uint32_t addr = sB + 2u * (uint32_t)((ko + (lane & 15)) * LDB
                                           + warp_n * 32 + nt * 8);
                ldsm_x2_trans(b[nt], addr);
            }
#pragma unroll
            for (int mt = 0; mt < 4; mt++)
#pragma unroll
                for (int nt = 0; nt < 4; nt++)
                    mma16816(c[mt][nt], a[mt], b[nt]);
        }
        __syncthreads();
    }

#pragma unroll
    for (int nt = 0; nt < 4; nt++) {
        int col = warp_n * 32 + nt * 8 + (lane & 3) * 2;
        float b0 = __ldg(bias + col);
        float b1 = __ldg(bias + col + 1);
#pragma unroll
        for (int mt = 0; mt < 4; mt++) {
            int row = bm + warp_m * 64 + mt * 16 + (lane >> 2);
            if (row < M) {
                float v0 = c[mt][nt][0] + b0;
                float v1 = c[mt][nt][1] + b1;
                __half2 h = __floats2half2_rn(v0 > 0.f ? v0 : 0.f,
                                              v1 > 0.f ? v1 : 0.f);
                *(__half2*)(g_hh + (size_t)row * HID + col) = h;
            }
            if (row + 8 < M) {
                float v0 = c[mt][nt][2] + b0;
                float v1 = c[mt][nt][3] + b1;
                __half2 h = __floats2half2_rn(v0 > 0.f ? v0 : 0.f,
                                              v1 > 0.f ? v1 : 0.f);
                *(__half2*)(g_hh + (size_t)(row + 8) * HID + col) = h;
            }
        }
    }
}

// ---------------------------------------------------------------------------
// CSR scan stages
// ---------------------------------------------------------------------------
__global__ void scan_block_kernel(int n) {
    __shared__ int warp_tot[32];
    int tid = threadIdx.x;
    int lane = tid & 31;
    int wid = tid >> 5;
    int i = blockIdx.x * 1024 + tid;
    int v = (i < n) ? g_deg[i] : 0;
    int x = v;
#pragma unroll
    for (int o = 1; o < 32; o <<= 1) {
        int y = __shfl_up_sync(0xFFFFFFFFu, x, o);
        if (lane >= o) x += y;
    }
    if (lane == 31) warp_tot[wid] = x;
    __syncthreads();
    if (wid == 0) {
        int t = warp_tot[lane];
#pragma unroll
        for (int o = 1; o < 32; o <<= 1) {
            int y = __shfl_up_sync(0xFFFFFFFFu, t, o);
            if (lane >= o) t += y;
        }
        warp_tot[lane] = t;
    }
    __syncthreads();
    int off = wid ? warp_tot[wid - 1] : 0;
    int incl = x + off;
    if (i < n) g_start[i] = incl - v;
    if (tid == 1023) g_bsum[blockIdx.x] = incl;
}

__global__ void add_off_kernel(int n, int nb) {
    __shared__ int boff_s;
    int tid = threadIdx.x;
    int b = blockIdx.x;
    if (tid < 32) {
        int acc = 0;
#pragma unroll
        for (int j = 0; j < 2; j++) {
            int idx = tid + j * 32;
            if (idx < b && idx < nb) acc += g_bsum[idx];
        }
#pragma unroll
        for (int o = 16; o; o >>= 1)
            acc += __shfl_xor_sync(0xFFFFFFFFu, acc, o);
        if (tid == 0) boff_s = acc;
    }
    __syncthreads();
    int i = b * 1024 + tid;
    if (i < n) {
        int s = g_start[i] + boff_s;
        g_start[i] = s;
        g_cursor[i] = s;
    }
}

// ---------------------------------------------------------------------------
// Mega-kernel B: blocks [0,Gs) do CSR scatter; the rest do layer-1 dots
// (si = h.w[:128], sj = h.w[128:], one warp per node).
// ---------------------------------------------------------------------------
__global__ void __launch_bounds__(256) scatter_dots_kernel(
        const int* __restrict__ ei, const float* __restrict__ w,
        int E, int n, int Gs) {
    if (blockIdx.x < Gs) {
        int is64 = detect_is64(ei);
        int base = blockIdx.x * 2048 + threadIdx.x;
#pragma unroll
        for (int i = 0; i < 8; i++) {
            int e = base + i * 256;
            if (e < E) {
                int s, d;
                if (is64) { s = ei[2 * e]; d = ei[2 * (E + e)]; }
                else      { s = ei[e];     d = ei[E + e]; }
                int pos = atomicAdd(&g_cursor[d], 1);
                g_sorted[pos] = s;
            }
        }
        return;
    }
    int node = (blockIdx.x - Gs) * 8 + (threadIdx.x >> 5);
    int lane = threadIdx.x & 31;
    if (node >= n) return;
    uint2 raw = *((const uint2*)(g_hh + (size_t)node * HID) + lane);
    float2 f01 = __half22float2(*(__half2*)&raw.x);
    float2 f23 = __half22float2(*(__half2*)&raw.y);
    float4 wi = ((const float4*)w)[lane];
    float4 wj = ((const float4*)w)[32 + lane];
    float si = f01.x * wi.x + f01.y * wi.y + f23.x * wi.z + f23.y * wi.w;
    float sj = f01.x * wj.x + f01.y * wj.y + f23.x * wj.z + f23.y * wj.w;
#pragma unroll
    for (int o = 16; o; o >>= 1) {
        si += __shfl_xor_sync(0xFFFFFFFFu, si, o);
        sj += __shfl_xor_sync(0xFFFFFFFFu, sj, o);
    }
    if (lane == 0) { g_si[node] = si; g_sj[node] = sj; }
}

// ---------------------------------------------------------------------------
// Shared gather-accumulate: 2 edges per warp step, 16 lanes/edge, uint4 loads.
// After the xor(16) combine ALL lanes hold the full sums for features
// [sub*8, sub*8+8), sub = lane&15. Identical to the verified R7/R14 loop
// except the feature load uses L1::no_allocate.
// ---------------------------------------------------------------------------
__device__ __forceinline__ void agg_accum(const __half* __restrict__ feat,
                                          const float* __restrict__ sj_tab,
                                          int k0, int deg, float sib,
                                          int half, int sub, float* acc) {
#pragma unroll
    for (int r = 0; r < 8; r++) acc[r] = 0.f;
    int kend = k0 + deg;
#pragma unroll 4
    for (int k = k0 + half; k < kend; k += 2) {
        int s = g_sorted[k];
        float z = sib + sj_tab[s];
        float alpha = 1.0f / (1.0f + __expf(-z));
        uint4 raw = ldg_na_v4((const uint4*)(feat + (size_t)s * HID) + sub);
        float2 f0 = __half22float2(*(__half2*)&raw.x);
        float2 f1 = __half22float2(*(__half2*)&raw.y);
        float2 f2 = __half22float2(*(__half2*)&raw.z);
        float2 f3 = __half22float2(*(__half2*)&raw.w);
        acc[0] += alpha * f0.x; acc[1] += alpha * f0.y;
        acc[2] += alpha * f1.x; acc[3] += alpha * f1.y;
        acc[4] += alpha * f2.x; acc[5] += alpha * f2.y;
        acc[6] += alpha * f3.x; acc[7] += alpha * f3.y;
    }
#pragma unroll
    for (int r = 0; r < 8; r++)
        acc[r] += __shfl_xor_sync(0xFFFFFFFFu, acc[r], 16);
}

// ---------------------------------------------------------------------------
// Layer 1 + fused layer-2 dots:
// g_hbh[d] = fp16(relu(acc/max(deg,1))); g_si2/g_sj2[d] = hb . att2_w halves.
// ---------------------------------------------------------------------------
__global__ void agg1_kernel(const float* __restrict__ bptr,
                            const float* __restrict__ att2w, int n) {
    int d = (blockIdx.x * blockDim.x + threadIdx.x) >> 5;
    int lane = threadIdx.x & 31;
    if (d >= n) return;
    int half = lane >> 4, sub = lane & 15;
    float acc[8];
    float sib = g_si[d] + bptr[0];
    agg_accum(g_hh, g_sj, g_start[d], g_deg[d], sib, half, sub, acc);
    int deg = g_deg[d];
    float inv = 1.0f / (float)(deg < 1 ? 1 : deg);
    __half2 h01 = __floats2half2_rn(fmaxf(acc[0] * inv, 0.f), fmaxf(acc[1] * inv, 0.f));
    __half2 h23 = __floats2half2_rn(fmaxf(acc[2] * inv, 0.f), fmaxf(acc[3] * inv, 0.f));
    __half2 h45 = __floats2half2_rn(fmaxf(acc[4] * inv, 0.f), fmaxf(acc[5] * inv, 0.f));
    __half2 h67 = __floats2half2_rn(fmaxf(acc[6] * inv, 0.f), fmaxf(acc[7] * inv, 0.f));
    if (half == 0) {
        uint4 u;
        u.x = *(unsigned*)&h01; u.y = *(unsigned*)&h23;
        u.z = *(unsigned*)&h45; u.w = *(unsigned*)&h67;
        *((uint4*)(g_hbh + (size_t)d * HID) + sub) = u;
    }
    // fused layer-2 dots from the fp16-rounded values
    float f[8];
    float2 t;
    t = __half22float2(h01); f[0] = t.x; f[1] = t.y;
    t = __half22float2(h23); f[2] = t.x; f[3] = t.y;
    t = __half22float2(h45); f[4] = t.x; f[5] = t.y;
    t = __half22float2(h67); f[6] = t.x; f[7] = t.y;
    int j = sub * 8;
    float4 wi0 = *(const float4*)(att2w + j);
    float4 wi1 = *(const float4*)(att2w + j + 4);
    float4 wj0 = *(const float4*)(att2w + 128 + j);
    float4 wj1 = *(const float4*)(att2w + 128 + j + 4);
    float si = f[0]*wi0.x + f[1]*wi0.y + f[2]*wi0.z + f[3]*wi0.w
             + f[4]*wi1.x + f[5]*wi1.y + f[6]*wi1.z + f[7]*wi1.w;
    float sj = f[0]*wj0.x + f[1]*wj0.y + f[2]*wj0.z + f[3]*wj0.w
             + f[4]*wj1.x + f[5]*wj1.y + f[6]*wj1.z + f[7]*wj1.w;
    if (half) { si = 0.f; sj = 0.f; }
#pragma unroll
    for (int o = 16; o; o >>= 1) {
        si += __shfl_xor_sync(0xFFFFFFFFu, si, o);
        sj += __shfl_xor_sync(0xFFFFFFFFu, sj, o);
    }
    if (lane == 0) { g_si2[d] = si; g_sj2[d] = sj; }
}

// ---------------------------------------------------------------------------
// Layer 2 + classifier; restores g_deg invariant (zeroes it after last use).
// ---------------------------------------------------------------------------
__global__ void agg2_cls_kernel(const float* __restrict__ bptr,
                                const float* __restrict__ clsw,
                                const float* __restrict__ clsb,
                                float* __restrict__ out, int n) {
    int d = (blockIdx.x * blockDim.x + threadIdx.x) >> 5;
    int lane = threadIdx.x & 31;
    if (d >= n) return;
    int half = lane >> 4, sub = lane & 15;
    float acc[8];
    float sib = g_si2[d] + bptr[0];
    agg_accum(g_hbh, g_sj2, g_start[d], g_deg[d], sib, half, sub, acc);
    int deg = g_deg[d];
    if (lane == 0) g_deg[d] = 0;   // restore invariant for next replay
    float inv = 1.0f / (float)(deg < 1 ? 1 : deg);
    float o0 = 0.f, o1 = 0.f;
#pragma unroll
    for (int r = 0; r < 8; r++) {
        float v = acc[r] * inv;
        int j = sub * 8 + r;
        o0 += v * clsw[j * 2];
        o1 += v * clsw[j * 2 + 1];
    }
#pragma unroll
    for (int o = 8; o; o >>= 1) {
        o0 += __shfl_xor_sync(0xFFFFFFFFu, o0, o);
        o1 += __shfl_xor_sync(0xFFFFFFFFu, o1, o);
    }
    if (lane == 0) {
        out[(size_t)d * 2 + 0] = o0 + clsb[0];
        out[(size_t)d * 2 + 1] = o1 + clsb[1];
    }
}

// ---------------------------------------------------------------------------
extern "C" void kernel_launch(void* const* d_in, const int* in_sizes, int n_in,
                              void* d_out, int out_size) {
    const float* x      = (const float*)d_in[0];
    const int*   ei     = (const int*)  d_in[1];
    const float* enc_w  = (const float*)d_in[2];
    const float* enc_b  = (const float*)d_in[3];
    const float* att1_w = (const float*)d_in[4];
    const float* att1_b = (const float*)d_in[5];
    const float* att2_w = (const float*)d_in[6];
    const float* att2_b = (const float*)d_in[7];
    const float* cls_w  = (const float*)d_in[8];
    const float* cls_b  = (const float*)d_in[9];
    float* out = (float*)d_out;

    int N = in_sizes[0] / 256;
    int E = in_sizes[1] / 2;
    int nb = (N + 1023) / 1024;
    int Ggemm = (N + 127) / 128;
    int Gh = (E + 2047) / 2048;
    int Gd = (N + 7) / 8;

    // A: encoder GEMM (tensor cores) overlapped with dst histogram
    gemm_hist_kernel<<<Ggemm + Gh, 256>>>(x, enc_w, enc_b, ei, N, E, Ggemm);
    // CSR offsets
    scan_block_kernel<<<nb, 1024>>>(N);
    add_off_kernel<<<nb, 1024>>>(N, nb);
    // B: CSR scatter overlapped with layer-1 attention dots
    scatter_dots_kernel<<<Gh + Gd, 256>>>(ei, att1_w, E, N, Gh);
    // Layer 1 (+ fused layer-2 dots)
    agg1_kernel<<<Gd, 256>>>(att1_b, att2_w, N);
    // Layer 2 + classifier (+ deg invariant restore)
    agg2_cls_kernel<<<Gd, 256>>>(att2_b, cls_w, cls_b, out, N);
}